// round 2
// baseline (speedup 1.0000x reference)
#include <cuda_runtime.h>

#define HID 128
#define TILE 64
#define NTHREADS 256
#define NMAX 50000

// Scratch (device globals: allocation-free rule)
__device__ float g_A[NMAX * 128];    // h @ eW1[0:128]   gathered by row
__device__ float g_B[NMAX * 128];    // h @ eW1[128:256] gathered by col
__device__ float g_agg[NMAX * 128];  // segment_sum(m, row)
__device__ int   g_is64;             // edge_index dtype flag

__device__ __forceinline__ float silu(float x) { return x / (1.0f + __expf(-x)); }
__device__ __forceinline__ float4 silu4(float4 v) {
    return make_float4(silu(v.x), silu(v.y), silu(v.z), silu(v.w));
}
__device__ __forceinline__ void fma4(float4& a, float s, float4 w) {
    a.x = fmaf(s, w.x, a.x); a.y = fmaf(s, w.y, a.y);
    a.z = fmaf(s, w.z, a.z); a.w = fmaf(s, w.w, a.w);
}

// ---------------------------------------------------------------------------
// detect edge_index dtype: int64 values (all in [0,N)) vs int32 pairs
// ---------------------------------------------------------------------------
__global__ void detect_kernel(const void* __restrict__ ei, int N, int E) {
    if (threadIdx.x == 0 && blockIdx.x == 0) {
        const long long* p = (const long long*)ei;
        int n = (E < 256) ? E : 256;
        int ok = 1;
        for (int i = 0; i < n; i++) {
            long long v = p[i];
            if (v < 0 || v >= (long long)N) { ok = 0; break; }
        }
        g_is64 = ok;
    }
}

// ---------------------------------------------------------------------------
// init: zero agg, pos_out = pos
// ---------------------------------------------------------------------------
__global__ void init_kernel(const float* __restrict__ pos, float* __restrict__ pos_out, int N) {
    int i = blockIdx.x * blockDim.x + threadIdx.x;
    if (i < N * 128) g_agg[i] = 0.0f;
    if (i < N * 3) pos_out[i] = pos[i];
}

// ---------------------------------------------------------------------------
// precompute: A = h @ eW1[0:128,:], B = h @ eW1[128:256,:]
// ---------------------------------------------------------------------------
#define PRE_SMEM ((64 * 132 + 16384) * 4)
__global__ __launch_bounds__(NTHREADS) void pre_kernel(
    const float* __restrict__ h, const float* __restrict__ eW1, int N)
{
    extern __shared__ float sm[];
    float* h_sm = sm;              // 64 * 132
    float* w_sm = sm + 64 * 132;   // 128 * 128

    int tid = threadIdx.x;
    int n0 = blockIdx.x * 64;
    for (int idx = tid; idx < 64 * 128; idx += NTHREADS) {
        int e = idx >> 7, k = idx & 127;
        int node = n0 + e;
        h_sm[e * 132 + k] = (node < N) ? h[node * 128 + k] : 0.0f;
    }
    const float4* hf4 = (const float4*)h_sm;
    int wid = tid >> 5, lane = tid & 31, ebase = wid * 8;

    for (int half = 0; half < 2; half++) {
        __syncthreads();
        for (int i = tid; i < 16384; i += NTHREADS) w_sm[i] = eW1[half * 16384 + i];
        __syncthreads();
        const float4* wf4 = (const float4*)w_sm;
        float4 acc[8];
        #pragma unroll
        for (int e = 0; e < 8; e++) acc[e] = make_float4(0.f, 0.f, 0.f, 0.f);
        for (int k0 = 0; k0 < 128; k0 += 4) {
            float4 w0 = wf4[(k0 + 0) * 32 + lane];
            float4 w1 = wf4[(k0 + 1) * 32 + lane];
            float4 w2 = wf4[(k0 + 2) * 32 + lane];
            float4 w3 = wf4[(k0 + 3) * 32 + lane];
            #pragma unroll
            for (int e = 0; e < 8; e++) {
                float4 mv = hf4[(ebase + e) * 33 + (k0 >> 2)];
                fma4(acc[e], mv.x, w0); fma4(acc[e], mv.y, w1);
                fma4(acc[e], mv.z, w2); fma4(acc[e], mv.w, w3);
            }
        }
        float* dst = (half == 0) ? g_A : g_B;
        #pragma unroll
        for (int e = 0; e < 8; e++) {
            int node = n0 + ebase + e;
            if (node < N) ((float4*)dst)[node * 32 + lane] = acc[e];
        }
    }
}

// ---------------------------------------------------------------------------
// fused edge kernel (persistent). 64 edges / tile, 256 threads, ~199KB smem.
// ---------------------------------------------------------------------------
#define EDGE_SMEM (50944 * 4)
__global__ __launch_bounds__(NTHREADS) void edge_kernel(
    const float* __restrict__ pos, const float* __restrict__ edge_attr,
    const void* __restrict__ ei_raw,
    const float* __restrict__ eW1, const float* __restrict__ eb1,
    const float* __restrict__ eW2, const float* __restrict__ eb2,
    const float* __restrict__ cW1, const float* __restrict__ cb1,
    const float* __restrict__ cW2, const float* __restrict__ cb2,
    float* __restrict__ pos_out, int N, int E)
{
    extern __shared__ float sm[];
    float* sW2   = sm;                 // 16384
    float* sC1   = sm + 16384;         // 16384
    float* m_sm  = sm + 32768;         // 64*132
    float* m2_sm = sm + 41216;         // 64*132
    float* sv    = sm + 49664;         // w_rn(0) w_ea(128) eb1(256) eb2(384) cb1(512) cw2(640)
    float* meta  = sm + 50432;
    int*   rowi  = (int*)meta;         // 64
    int*   coli  = (int*)(meta + 64);  // 64
    float* radx = meta + 128; float* rady = meta + 192; float* radz = meta + 256;
    float* rn_s = meta + 320; float* irn_s = meta + 384; float* ea_s = meta + 448;

    int tid = threadIdx.x;
    for (int i = tid; i < 16384; i += NTHREADS) { sW2[i] = eW2[i]; sC1[i] = cW1[i]; }
    for (int i = tid; i < 128; i += NTHREADS) {
        sv[i]       = eW1[256 * 128 + i];
        sv[128 + i] = eW1[257 * 128 + i];
        sv[256 + i] = eb1[i];
        sv[384 + i] = eb2[i];
        sv[512 + i] = cb1[i];
        sv[640 + i] = cW2[i];
    }
    float cb2v = cb2[0];
    int is64 = g_is64;
    const long long* ei64 = (const long long*)ei_raw;
    const int*       ei32 = (const int*)ei_raw;

    int wid = tid >> 5, lane = tid & 31, ebase = wid * 8;
    const float4* W2f = (const float4*)sW2;
    const float4* C1f = (const float4*)sC1;
    const float4* Mf  = (const float4*)m_sm;
    const float4* M2f = (const float4*)m2_sm;

    __syncthreads();
    float4 b2  = ((const float4*)(sv + 384))[lane];
    float4 bc1 = ((const float4*)(sv + 512))[lane];
    float4 cwv = ((const float4*)(sv + 640))[lane];

    int ntiles = (E + TILE - 1) / TILE;
    for (int t = blockIdx.x; t < ntiles; t += gridDim.x) {
        int e0 = t * TILE;
        int cnt = min(TILE, E - e0);
        __syncthreads();
        if (tid < TILE) {
            if (tid < cnt) {
                int e = e0 + tid;
                int r, c;
                if (is64) { r = (int)ei64[e]; c = (int)ei64[E + e]; }
                else      { r = ei32[e];      c = ei32[E + e]; }
                r = min(max(r, 0), N - 1);
                c = min(max(c, 0), N - 1);
                float dx = pos[r * 3 + 0] - pos[c * 3 + 0];
                float dy = pos[r * 3 + 1] - pos[c * 3 + 1];
                float dz = pos[r * 3 + 2] - pos[c * 3 + 2];
                float nrm = sqrtf(dx * dx + dy * dy + dz * dz);
                float rn = fmaxf(nrm, 1e-8f);
                rowi[tid] = r; coli[tid] = c;
                radx[tid] = dx; rady[tid] = dy; radz[tid] = dz;
                rn_s[tid] = rn; irn_s[tid] = 1.0f / rn;
                ea_s[tid] = edge_attr[e];
            } else {
                rowi[tid] = 0; coli[tid] = 0;
                radx[tid] = 0; rady[tid] = 0; radz[tid] = 0;
                rn_s[tid] = 1.0f; irn_s[tid] = 1.0f; ea_s[tid] = 0.0f;
            }
        }
        __syncthreads();

        // m = silu(A[row] + B[col] + rn*w_rn + ea*w_ea + eb1)
        for (int idx = tid; idx < TILE * 128; idx += NTHREADS) {
            int e = idx >> 7, k = idx & 127;
            int r = rowi[e], c = coli[e];
            float v = g_A[r * 128 + k] + g_B[c * 128 + k];
            v = fmaf(rn_s[e], sv[k], v);
            v = fmaf(ea_s[e], sv[128 + k], v);
            v += sv[256 + k];
            m_sm[e * 132 + k] = silu(v);
        }
        __syncthreads();

        // m2 = silu(m @ eW2 + eb2)
        {
            float4 acc[8];
            #pragma unroll
            for (int e = 0; e < 8; e++) acc[e] = b2;
            for (int k0 = 0; k0 < 128; k0 += 4) {
                float4 w0 = W2f[(k0 + 0) * 32 + lane];
                float4 w1 = W2f[(k0 + 1) * 32 + lane];
                float4 w2 = W2f[(k0 + 2) * 32 + lane];
                float4 w3 = W2f[(k0 + 3) * 32 + lane];
                #pragma unroll
                for (int e = 0; e < 8; e++) {
                    float4 mv = Mf[(ebase + e) * 33 + (k0 >> 2)];
                    fma4(acc[e], mv.x, w0); fma4(acc[e], mv.y, w1);
                    fma4(acc[e], mv.z, w2); fma4(acc[e], mv.w, w3);
                }
            }
            #pragma unroll
            for (int e = 0; e < 8; e++)
                ((float4*)m2_sm)[(ebase + e) * 33 + lane] = silu4(acc[e]);
        }
        __syncthreads();

        // t = silu(m2 @ cW1 + cb1); coord = t . cW2 + cb2; pos atomics
        {
            float4 acc[8];
            #pragma unroll
            for (int e = 0; e < 8; e++) acc[e] = bc1;
            for (int k0 = 0; k0 < 128; k0 += 4) {
                float4 w0 = C1f[(k0 + 0) * 32 + lane];
                float4 w1 = C1f[(k0 + 1) * 32 + lane];
                float4 w2 = C1f[(k0 + 2) * 32 + lane];
                float4 w3 = C1f[(k0 + 3) * 32 + lane];
                #pragma unroll
                for (int e = 0; e < 8; e++) {
                    float4 mv = M2f[(ebase + e) * 33 + (k0 >> 2)];
                    fma4(acc[e], mv.x, w0); fma4(acc[e], mv.y, w1);
                    fma4(acc[e], mv.z, w2); fma4(acc[e], mv.w, w3);
                }
            }
            float part[8];
            #pragma unroll
            for (int e = 0; e < 8; e++) {
                float4 tt = silu4(acc[e]);
                part[e] = tt.x * cwv.x + tt.y * cwv.y + tt.z * cwv.z + tt.w * cwv.w;
            }
            #pragma unroll
            for (int e = 0; e < 8; e++) {
                #pragma unroll
                for (int off = 16; off; off >>= 1)
                    part[e] += __shfl_xor_sync(0xffffffffu, part[e], off);
            }
            int el = ebase + lane;
            if (lane < 8 && el < cnt) {
                float cd = 0.0f;
                #pragma unroll
                for (int e = 0; e < 8; e++) if (lane == e) cd = part[e];
                float s = (cd + cb2v) * irn_s[el];
                int r = rowi[el];
                atomicAdd(&pos_out[r * 3 + 0], s * radx[el]);
                atomicAdd(&pos_out[r * 3 + 1], s * rady[el]);
                atomicAdd(&pos_out[r * 3 + 2], s * radz[el]);
            }
        }
        // agg[row] += m2 (coalesced 128B rows per warp)
        for (int idx = tid; idx < cnt * 128; idx += NTHREADS) {
            int e = idx >> 7, k = idx & 127;
            atomicAdd(&g_agg[rowi[e] * 128 + k], m2_sm[e * 132 + k]);
        }
    }
}

// ---------------------------------------------------------------------------
// node MLP: hn = silu([h,agg] @ nW1 + nb1); h_new = h + hn @ nW2 + nb2
// ---------------------------------------------------------------------------
#define NODE_SMEM ((64 * 260 + 16384 + 64 * 132) * 4)
__global__ __launch_bounds__(NTHREADS) void node_kernel(
    const float* __restrict__ h,
    const float* __restrict__ nW1, const float* __restrict__ nb1,
    const float* __restrict__ nW2, const float* __restrict__ nb2,
    float* __restrict__ h_out, int N)
{
    extern __shared__ float sm[];
    float* x_sm  = sm;             // 64*260 (cols 0..127 = h, 128..255 = agg)
    float* w_sm  = sm + 16640;     // 128*128
    float* hn_sm = sm + 33024;     // 64*132

    int tid = threadIdx.x, wid = tid >> 5, lane = tid & 31, ebase = wid * 8;
    int n0 = blockIdx.x * 64;
    for (int idx = tid; idx < 64 * 256; idx += NTHREADS) {
        int e = idx >> 8, k = idx & 255;
        int node = n0 + e;
        float v = 0.0f;
        if (node < N) v = (k < 128) ? h[node * 128 + k] : g_agg[node * 128 + (k - 128)];
        x_sm[e * 260 + k] = v;
    }
    const float4* Xf = (const float4*)x_sm;  // row stride 65 float4

    float4 acc[8];
    float4 bn1 = ((const float4*)nb1)[lane];
    #pragma unroll
    for (int e = 0; e < 8; e++) acc[e] = bn1;

    for (int half = 0; half < 2; half++) {
        __syncthreads();
        for (int i = tid; i < 16384; i += NTHREADS) w_sm[i] = nW1[half * 16384 + i];
        __syncthreads();
        const float4* Wf = (const float4*)w_sm;
        for (int k0 = 0; k0 < 128; k0 += 4) {
            float4 w0 = Wf[(k0 + 0) * 32 + lane];
            float4 w1 = Wf[(k0 + 1) * 32 + lane];
            float4 w2 = Wf[(k0 + 2) * 32 + lane];
            float4 w3 = Wf[(k0 + 3) * 32 + lane];
            #pragma unroll
            for (int e = 0; e < 8; e++) {
                float4 mv = Xf[(ebase + e) * 65 + half * 32 + (k0 >> 2)];
                fma4(acc[e], mv.x, w0); fma4(acc[e], mv.y, w1);
                fma4(acc[e], mv.z, w2); fma4(acc[e], mv.w, w3);
            }
        }
    }
    #pragma unroll
    for (int e = 0; e < 8; e++)
        ((float4*)hn_sm)[(ebase + e) * 33 + lane] = silu4(acc[e]);
    __syncthreads();
    for (int i = tid; i < 16384; i += NTHREADS) w_sm[i] = nW2[i];
    __syncthreads();

    const float4* Wf = (const float4*)w_sm;
    const float4* Hf = (const float4*)hn_sm;
    float4 bn2 = ((const float4*)nb2)[lane];
    #pragma unroll
    for (int e = 0; e < 8; e++) acc[e] = bn2;
    for (int k0 = 0; k0 < 128; k0 += 4) {
        float4 w0 = Wf[(k0 + 0) * 32 + lane];
        float4 w1 = Wf[(k0 + 1) * 32 + lane];
        float4 w2 = Wf[(k0 + 2) * 32 + lane];
        float4 w3 = Wf[(k0 + 3) * 32 + lane];
        #pragma unroll
        for (int e = 0; e < 8; e++) {
            float4 mv = Hf[(ebase + e) * 33 + (k0 >> 2)];
            fma4(acc[e], mv.x, w0); fma4(acc[e], mv.y, w1);
            fma4(acc[e], mv.z, w2); fma4(acc[e], mv.w, w3);
        }
    }
    #pragma unroll
    for (int e = 0; e < 8; e++) {
        int node = n0 + ebase + e;
        if (node < N) {
            float4 r = Xf[(ebase + e) * 65 + lane];  // h residual
            acc[e].x += r.x; acc[e].y += r.y; acc[e].z += r.z; acc[e].w += r.w;
            ((float4*)h_out)[node * 32 + lane] = acc[e];
        }
    }
}

// ---------------------------------------------------------------------------
extern "C" void kernel_launch(void* const* d_in, const int* in_sizes, int n_in,
                              void* d_out, int out_size)
{
    const float* h   = (const float*)d_in[0];
    const float* pos = (const float*)d_in[1];
    const float* ea  = (const float*)d_in[2];
    const void*  ei  = d_in[3];
    const float* eW1 = (const float*)d_in[4];
    const float* eb1 = (const float*)d_in[5];
    const float* eW2 = (const float*)d_in[6];
    const float* eb2 = (const float*)d_in[7];
    const float* nW1 = (const float*)d_in[8];
    const float* nb1 = (const float*)d_in[9];
    const float* nW2 = (const float*)d_in[10];
    const float* nb2 = (const float*)d_in[11];
    const float* cW1 = (const float*)d_in[12];
    const float* cb1 = (const float*)d_in[13];
    const float* cW2 = (const float*)d_in[14];
    const float* cb2 = (const float*)d_in[15];

    int N = in_sizes[0] / 128;
    int E = in_sizes[2];
    float* h_out   = (float*)d_out;
    float* pos_out = h_out + (size_t)N * 128;

    cudaFuncSetAttribute(pre_kernel,  cudaFuncAttributeMaxDynamicSharedMemorySize, PRE_SMEM);
    cudaFuncSetAttribute(edge_kernel, cudaFuncAttributeMaxDynamicSharedMemorySize, EDGE_SMEM);
    cudaFuncSetAttribute(node_kernel, cudaFuncAttributeMaxDynamicSharedMemorySize, NODE_SMEM);

    int nsm = 148;
    cudaDeviceGetAttribute(&nsm, cudaDevAttrMultiProcessorCount, 0);

    detect_kernel<<<1, 32>>>(ei, N, E);
    init_kernel<<<(N * 128 + 255) / 256, 256>>>(pos, pos_out, N);
    pre_kernel<<<(N + 63) / 64, NTHREADS, PRE_SMEM>>>(h, eW1, N);
    edge_kernel<<<nsm, NTHREADS, EDGE_SMEM>>>(pos, ea, ei, eW1, eb1, eW2, eb2,
                                              cW1, cb1, cW2, cb2, pos_out, N, E);
    node_kernel<<<(N + 63) / 64, NTHREADS, NODE_SMEM>>>(h, nW1, nb1, nW2, nb2, h_out, N);
}

// round 3
// speedup vs baseline: 1.9886x; 1.9886x over previous
#include <cuda_runtime.h>

#define HID 128
#define TILE 64
#define NTHREADS 256
#define NMAX 50000

// Scratch (device globals: allocation-free rule)
__device__ float g_A[NMAX * 128];    // h @ eW1[0:128]   gathered by row
__device__ float g_B[NMAX * 128];    // h @ eW1[128:256] gathered by col
__device__ float g_agg[NMAX * 128];  // segment_sum(m, row)
__device__ int   g_is64;             // edge_index dtype flag

__device__ __forceinline__ float silu(float x) { return x / (1.0f + __expf(-x)); }
__device__ __forceinline__ float4 silu4(float4 v) {
    return make_float4(silu(v.x), silu(v.y), silu(v.z), silu(v.w));
}
__device__ __forceinline__ void fma4(float4& a, float s, float4 w) {
    a.x = fmaf(s, w.x, a.x); a.y = fmaf(s, w.y, a.y);
    a.z = fmaf(s, w.z, a.z); a.w = fmaf(s, w.w, a.w);
}
// packed fp32x2 FMA: d = a*b + d  (2 fp32 FMAs in one issue slot)
__device__ __forceinline__ void ffma2(unsigned long long& d,
                                      unsigned long long a, unsigned long long b) {
    asm("fma.rn.f32x2 %0, %1, %2, %0;" : "+l"(d) : "l"(a), "l"(b));
}
__device__ __forceinline__ float hsum2(unsigned long long v) {
    float lo = __uint_as_float((unsigned)(v & 0xffffffffull));
    float hi = __uint_as_float((unsigned)(v >> 32));
    return lo + hi;
}

// ---------------------------------------------------------------------------
// detect edge_index dtype: int64 values (all in [0,N)) vs int32 pairs
// ---------------------------------------------------------------------------
__global__ void detect_kernel(const void* __restrict__ ei, int N, int E) {
    if (threadIdx.x == 0 && blockIdx.x == 0) {
        const long long* p = (const long long*)ei;
        int n = (E < 256) ? E : 256;
        int ok = 1;
        for (int i = 0; i < n; i++) {
            long long v = p[i];
            if (v < 0 || v >= (long long)N) { ok = 0; break; }
        }
        g_is64 = ok;
    }
}

// ---------------------------------------------------------------------------
// init: zero agg, pos_out = pos
// ---------------------------------------------------------------------------
__global__ void init_kernel(const float* __restrict__ pos, float* __restrict__ pos_out, int N) {
    int i = blockIdx.x * blockDim.x + threadIdx.x;
    if (i < N * 128) g_agg[i] = 0.0f;
    if (i < N * 3) pos_out[i] = pos[i];
}

// ---------------------------------------------------------------------------
// precompute: A = h @ eW1[0:128,:], B = h @ eW1[128:256,:]
// ---------------------------------------------------------------------------
#define PRE_SMEM ((64 * 132 + 16384) * 4)
__global__ __launch_bounds__(NTHREADS) void pre_kernel(
    const float* __restrict__ h, const float* __restrict__ eW1, int N)
{
    extern __shared__ float sm[];
    float* h_sm = sm;              // 64 * 132
    float* w_sm = sm + 64 * 132;   // 128 * 128

    int tid = threadIdx.x;
    int n0 = blockIdx.x * 64;
    for (int idx = tid; idx < 64 * 128; idx += NTHREADS) {
        int e = idx >> 7, k = idx & 127;
        int node = n0 + e;
        h_sm[e * 132 + k] = (node < N) ? h[node * 128 + k] : 0.0f;
    }
    const float4* hf4 = (const float4*)h_sm;
    int wid = tid >> 5, lane = tid & 31, ebase = wid * 8;

    for (int half = 0; half < 2; half++) {
        __syncthreads();
        for (int i = tid; i < 16384; i += NTHREADS) w_sm[i] = eW1[half * 16384 + i];
        __syncthreads();
        const float4* wf4 = (const float4*)w_sm;
        float4 acc[8];
        #pragma unroll
        for (int e = 0; e < 8; e++) acc[e] = make_float4(0.f, 0.f, 0.f, 0.f);
        for (int k0 = 0; k0 < 128; k0 += 4) {
            float4 w0 = wf4[(k0 + 0) * 32 + lane];
            float4 w1 = wf4[(k0 + 1) * 32 + lane];
            float4 w2 = wf4[(k0 + 2) * 32 + lane];
            float4 w3 = wf4[(k0 + 3) * 32 + lane];
            #pragma unroll
            for (int e = 0; e < 8; e++) {
                float4 mv = hf4[(ebase + e) * 33 + (k0 >> 2)];
                fma4(acc[e], mv.x, w0); fma4(acc[e], mv.y, w1);
                fma4(acc[e], mv.z, w2); fma4(acc[e], mv.w, w3);
            }
        }
        float* dst = (half == 0) ? g_A : g_B;
        #pragma unroll
        for (int e = 0; e < 8; e++) {
            int node = n0 + ebase + e;
            if (node < N) ((float4*)dst)[node * 32 + lane] = acc[e];
        }
    }
}

// ---------------------------------------------------------------------------
// fused edge kernel (persistent). 64 edges / tile, 256 threads.
// Transposed weights [out][k] + packed f32x2 k-pair accumulation.
// SMEM (floats): W2t 16896 | C1t 16896 | m 8448 | m2 8448 | sv 768 | meta 512
// ---------------------------------------------------------------------------
#define EDGE_SMEM (51968 * 4)
__global__ __launch_bounds__(NTHREADS) void edge_kernel(
    const float* __restrict__ pos, const float* __restrict__ edge_attr,
    const void* __restrict__ ei_raw,
    const float* __restrict__ eW1, const float* __restrict__ eb1,
    const float* __restrict__ eW2, const float* __restrict__ eb2,
    const float* __restrict__ cW1, const float* __restrict__ cb1,
    const float* __restrict__ cW2, const float* __restrict__ cb2,
    float* __restrict__ pos_out, int N, int E)
{
    extern __shared__ float sm[];
    float* sW2t  = sm;                 // 128 rows * 132
    float* sC1t  = sm + 16896;         // 128 rows * 132
    float* m_sm  = sm + 33792;         // 64*132
    float* m2_sm = sm + 42240;         // 64*132
    float* sv    = sm + 50688;         // w_rn(0) w_ea(128) eb1(256) eb2(384) cb1(512) cw2(640)
    float* meta  = sm + 51456;
    int*   rowi  = (int*)meta;         // 64
    int*   coli  = (int*)(meta + 64);  // 64
    float* radx = meta + 128; float* rady = meta + 192; float* radz = meta + 256;
    float* rn_s = meta + 320; float* irn_s = meta + 384; float* ea_s = meta + 448;

    int tid = threadIdx.x;
    // transpose weights into [out][k] with row stride 132 (33 x 16B, odd)
    for (int i = tid; i < 16384; i += NTHREADS) {
        int k = i >> 7, o = i & 127;
        sW2t[o * 132 + k] = eW2[i];
        sC1t[o * 132 + k] = cW1[i];
    }
    for (int i = tid; i < 128; i += NTHREADS) {
        sv[i]       = eW1[256 * 128 + i];
        sv[128 + i] = eW1[257 * 128 + i];
        sv[256 + i] = eb1[i];
        sv[384 + i] = eb2[i];
        sv[512 + i] = cb1[i];
        sv[640 + i] = cW2[i];
    }
    float cb2v = cb2[0];
    int is64 = g_is64;
    const long long* ei64 = (const long long*)ei_raw;
    const int*       ei32 = (const int*)ei_raw;

    int wid = tid >> 5, lane = tid & 31, ebase = wid * 8;
    const ulonglong2* W2u = (const ulonglong2*)sW2t;   // row stride 33
    const ulonglong2* C1u = (const ulonglong2*)sC1t;
    const ulonglong2* Mu  = (const ulonglong2*)m_sm;
    const ulonglong2* M2u = (const ulonglong2*)m2_sm;

    __syncthreads();
    float b2r[4], bc1r[4], cwr[4];
    #pragma unroll
    for (int j = 0; j < 4; j++) {
        b2r[j]  = sv[384 + j * 32 + lane];
        bc1r[j] = sv[512 + j * 32 + lane];
        cwr[j]  = sv[640 + j * 32 + lane];
    }

    int ntiles = (E + TILE - 1) / TILE;
    for (int t = blockIdx.x; t < ntiles; t += gridDim.x) {
        int e0 = t * TILE;
        int cnt = min(TILE, E - e0);
        __syncthreads();
        if (tid < TILE) {
            if (tid < cnt) {
                int e = e0 + tid;
                int r, c;
                if (is64) { r = (int)ei64[e]; c = (int)ei64[E + e]; }
                else      { r = ei32[e];      c = ei32[E + e]; }
                r = min(max(r, 0), N - 1);
                c = min(max(c, 0), N - 1);
                float dx = pos[r * 3 + 0] - pos[c * 3 + 0];
                float dy = pos[r * 3 + 1] - pos[c * 3 + 1];
                float dz = pos[r * 3 + 2] - pos[c * 3 + 2];
                float nrm = sqrtf(dx * dx + dy * dy + dz * dz);
                float rn = fmaxf(nrm, 1e-8f);
                rowi[tid] = r; coli[tid] = c;
                radx[tid] = dx; rady[tid] = dy; radz[tid] = dz;
                rn_s[tid] = rn; irn_s[tid] = 1.0f / rn;
                ea_s[tid] = edge_attr[e];
            } else {
                rowi[tid] = 0; coli[tid] = 0;
                radx[tid] = 0; rady[tid] = 0; radz[tid] = 0;
                rn_s[tid] = 1.0f; irn_s[tid] = 1.0f; ea_s[tid] = 0.0f;
            }
        }
        __syncthreads();

        // m = silu(A[row] + B[col] + rn*w_rn + ea*w_ea + eb1)   (float4)
        for (int idx = tid; idx < TILE * 32; idx += NTHREADS) {
            int e = idx >> 5, c = idx & 31;
            float4 a = ((const float4*)(g_A + rowi[e] * 128))[c];
            float4 b = ((const float4*)(g_B + coli[e] * 128))[c];
            float rn = rn_s[e], eav = ea_s[e];
            float4 wr = ((const float4*)sv)[c];
            float4 we = ((const float4*)(sv + 128))[c];
            float4 bb = ((const float4*)(sv + 256))[c];
            float4 v;
            v.x = fmaf(rn, wr.x, a.x + b.x); v.y = fmaf(rn, wr.y, a.y + b.y);
            v.z = fmaf(rn, wr.z, a.z + b.z); v.w = fmaf(rn, wr.w, a.w + b.w);
            v.x = fmaf(eav, we.x, v.x) + bb.x; v.y = fmaf(eav, we.y, v.y) + bb.y;
            v.z = fmaf(eav, we.z, v.z) + bb.z; v.w = fmaf(eav, we.w, v.w) + bb.w;
            ((float4*)(m_sm + e * 132))[c] = silu4(v);
        }
        __syncthreads();

        // m2 = silu(m @ eW2 + eb2)  — f32x2 k-pair microkernel
        {
            unsigned long long acc[8][4];
            #pragma unroll
            for (int e = 0; e < 8; e++)
                #pragma unroll
                for (int j = 0; j < 4; j++) acc[e][j] = 0ull;
            #pragma unroll 4
            for (int c = 0; c < 32; c++) {
                ulonglong2 w0 = W2u[(0 * 32 + lane) * 33 + c];
                ulonglong2 w1 = W2u[(1 * 32 + lane) * 33 + c];
                ulonglong2 w2 = W2u[(2 * 32 + lane) * 33 + c];
                ulonglong2 w3 = W2u[(3 * 32 + lane) * 33 + c];
                #pragma unroll
                for (int e = 0; e < 8; e++) {
                    ulonglong2 mv = Mu[(ebase + e) * 33 + c];
                    ffma2(acc[e][0], mv.x, w0.x); ffma2(acc[e][0], mv.y, w0.y);
                    ffma2(acc[e][1], mv.x, w1.x); ffma2(acc[e][1], mv.y, w1.y);
                    ffma2(acc[e][2], mv.x, w2.x); ffma2(acc[e][2], mv.y, w2.y);
                    ffma2(acc[e][3], mv.x, w3.x); ffma2(acc[e][3], mv.y, w3.y);
                }
            }
            #pragma unroll
            for (int e = 0; e < 8; e++)
                #pragma unroll
                for (int j = 0; j < 4; j++) {
                    float s = hsum2(acc[e][j]) + b2r[j];
                    m2_sm[(ebase + e) * 132 + j * 32 + lane] = silu(s);
                }
        }
        // no sync needed: each warp consumes only its own m2 rows

        // t = silu(m2 @ cW1 + cb1); coord = t . cW2 + cb2; pos atomics
        {
            unsigned long long acc[8][4];
            #pragma unroll
            for (int e = 0; e < 8; e++)
                #pragma unroll
                for (int j = 0; j < 4; j++) acc[e][j] = 0ull;
            #pragma unroll 4
            for (int c = 0; c < 32; c++) {
                ulonglong2 w0 = C1u[(0 * 32 + lane) * 33 + c];
                ulonglong2 w1 = C1u[(1 * 32 + lane) * 33 + c];
                ulonglong2 w2 = C1u[(2 * 32 + lane) * 33 + c];
                ulonglong2 w3 = C1u[(3 * 32 + lane) * 33 + c];
                #pragma unroll
                for (int e = 0; e < 8; e++) {
                    ulonglong2 mv = M2u[(ebase + e) * 33 + c];
                    ffma2(acc[e][0], mv.x, w0.x); ffma2(acc[e][0], mv.y, w0.y);
                    ffma2(acc[e][1], mv.x, w1.x); ffma2(acc[e][1], mv.y, w1.y);
                    ffma2(acc[e][2], mv.x, w2.x); ffma2(acc[e][2], mv.y, w2.y);
                    ffma2(acc[e][3], mv.x, w3.x); ffma2(acc[e][3], mv.y, w3.y);
                }
            }
            float part[8];
            #pragma unroll
            for (int e = 0; e < 8; e++) {
                float p = 0.0f;
                #pragma unroll
                for (int j = 0; j < 4; j++) {
                    float tt = silu(hsum2(acc[e][j]) + bc1r[j]);
                    p = fmaf(tt, cwr[j], p);
                }
                part[e] = p;
            }
            #pragma unroll
            for (int e = 0; e < 8; e++) {
                #pragma unroll
                for (int off = 16; off; off >>= 1)
                    part[e] += __shfl_xor_sync(0xffffffffu, part[e], off);
            }
            int el = ebase + lane;
            if (lane < 8 && el < cnt) {
                float cd = 0.0f;
                #pragma unroll
                for (int e = 0; e < 8; e++) if (lane == e) cd = part[e];
                float s = (cd + cb2v) * irn_s[el];
                int r = rowi[el];
                atomicAdd(&pos_out[r * 3 + 0], s * radx[el]);
                atomicAdd(&pos_out[r * 3 + 1], s * rady[el]);
                atomicAdd(&pos_out[r * 3 + 2], s * radz[el]);
            }
        }
        __syncthreads();   // m2_sm fully written before cross-warp agg read
        // agg[row] += m2 (coalesced 128B rows per warp)
        for (int idx = tid; idx < cnt * 128; idx += NTHREADS) {
            int e = idx >> 7, k = idx & 127;
            atomicAdd(&g_agg[rowi[e] * 128 + k], m2_sm[e * 132 + k]);
        }
    }
}

// ---------------------------------------------------------------------------
// node MLP: hn = silu([h,agg] @ nW1 + nb1); h_new = h + hn @ nW2 + nb2
// ---------------------------------------------------------------------------
#define NODE_SMEM ((64 * 260 + 16384 + 64 * 132) * 4)
__global__ __launch_bounds__(NTHREADS) void node_kernel(
    const float* __restrict__ h,
    const float* __restrict__ nW1, const float* __restrict__ nb1,
    const float* __restrict__ nW2, const float* __restrict__ nb2,
    float* __restrict__ h_out, int N)
{
    extern __shared__ float sm[];
    float* x_sm  = sm;             // 64*260 (cols 0..127 = h, 128..255 = agg)
    float* w_sm  = sm + 16640;     // 128*128
    float* hn_sm = sm + 33024;     // 64*132

    int tid = threadIdx.x, wid = tid >> 5, lane = tid & 31, ebase = wid * 8;
    int n0 = blockIdx.x * 64;
    for (int idx = tid; idx < 64 * 256; idx += NTHREADS) {
        int e = idx >> 8, k = idx & 255;
        int node = n0 + e;
        float v = 0.0f;
        if (node < N) v = (k < 128) ? h[node * 128 + k] : g_agg[node * 128 + (k - 128)];
        x_sm[e * 260 + k] = v;
    }
    const float4* Xf = (const float4*)x_sm;  // row stride 65 float4

    float4 acc[8];
    float4 bn1 = ((const float4*)nb1)[lane];
    #pragma unroll
    for (int e = 0; e < 8; e++) acc[e] = bn1;

    for (int half = 0; half < 2; half++) {
        __syncthreads();
        for (int i = tid; i < 16384; i += NTHREADS) w_sm[i] = nW1[half * 16384 + i];
        __syncthreads();
        const float4* Wf = (const float4*)w_sm;
        for (int k0 = 0; k0 < 128; k0 += 4) {
            float4 w0 = Wf[(k0 + 0) * 32 + lane];
            float4 w1 = Wf[(k0 + 1) * 32 + lane];
            float4 w2 = Wf[(k0 + 2) * 32 + lane];
            float4 w3 = Wf[(k0 + 3) * 32 + lane];
            #pragma unroll
            for (int e = 0; e < 8; e++) {
                float4 mv = Xf[(ebase + e) * 65 + half * 32 + (k0 >> 2)];
                fma4(acc[e], mv.x, w0); fma4(acc[e], mv.y, w1);
                fma4(acc[e], mv.z, w2); fma4(acc[e], mv.w, w3);
            }
        }
    }
    #pragma unroll
    for (int e = 0; e < 8; e++)
        ((float4*)hn_sm)[(ebase + e) * 33 + lane] = silu4(acc[e]);
    __syncthreads();
    for (int i = tid; i < 16384; i += NTHREADS) w_sm[i] = nW2[i];
    __syncthreads();

    const float4* Wf = (const float4*)w_sm;
    const float4* Hf = (const float4*)hn_sm;
    float4 bn2 = ((const float4*)nb2)[lane];
    #pragma unroll
    for (int e = 0; e < 8; e++) acc[e] = bn2;
    for (int k0 = 0; k0 < 128; k0 += 4) {
        float4 w0 = Wf[(k0 + 0) * 32 + lane];
        float4 w1 = Wf[(k0 + 1) * 32 + lane];
        float4 w2 = Wf[(k0 + 2) * 32 + lane];
        float4 w3 = Wf[(k0 + 3) * 32 + lane];
        #pragma unroll
        for (int e = 0; e < 8; e++) {
            float4 mv = Hf[(ebase + e) * 33 + (k0 >> 2)];
            fma4(acc[e], mv.x, w0); fma4(acc[e], mv.y, w1);
            fma4(acc[e], mv.z, w2); fma4(acc[e], mv.w, w3);
        }
    }
    #pragma unroll
    for (int e = 0; e < 8; e++) {
        int node = n0 + ebase + e;
        if (node < N) {
            float4 r = Xf[(ebase + e) * 65 + lane];  // h residual
            acc[e].x += r.x; acc[e].y += r.y; acc[e].z += r.z; acc[e].w += r.w;
            ((float4*)h_out)[node * 32 + lane] = acc[e];
        }
    }
}

// ---------------------------------------------------------------------------
extern "C" void kernel_launch(void* const* d_in, const int* in_sizes, int n_in,
                              void* d_out, int out_size)
{
    const float* h   = (const float*)d_in[0];
    const float* pos = (const float*)d_in[1];
    const float* ea  = (const float*)d_in[2];
    const void*  ei  = d_in[3];
    const float* eW1 = (const float*)d_in[4];
    const float* eb1 = (const float*)d_in[5];
    const float* eW2 = (const float*)d_in[6];
    const float* eb2 = (const float*)d_in[7];
    const float* nW1 = (const float*)d_in[8];
    const float* nb1 = (const float*)d_in[9];
    const float* nW2 = (const float*)d_in[10];
    const float* nb2 = (const float*)d_in[11];
    const float* cW1 = (const float*)d_in[12];
    const float* cb1 = (const float*)d_in[13];
    const float* cW2 = (const float*)d_in[14];
    const float* cb2 = (const float*)d_in[15];

    int N = in_sizes[0] / 128;
    int E = in_sizes[2];
    float* h_out   = (float*)d_out;
    float* pos_out = h_out + (size_t)N * 128;

    cudaFuncSetAttribute(pre_kernel,  cudaFuncAttributeMaxDynamicSharedMemorySize, PRE_SMEM);
    cudaFuncSetAttribute(edge_kernel, cudaFuncAttributeMaxDynamicSharedMemorySize, EDGE_SMEM);
    cudaFuncSetAttribute(node_kernel, cudaFuncAttributeMaxDynamicSharedMemorySize, NODE_SMEM);

    int nsm = 148;
    cudaDeviceGetAttribute(&nsm, cudaDevAttrMultiProcessorCount, 0);

    detect_kernel<<<1, 32>>>(ei, N, E);
    init_kernel<<<(N * 128 + 255) / 256, 256>>>(pos, pos_out, N);
    pre_kernel<<<(N + 63) / 64, NTHREADS, PRE_SMEM>>>(h, eW1, N);
    edge_kernel<<<nsm, NTHREADS, EDGE_SMEM>>>(pos, ea, ei, eW1, eb1, eW2, eb2,
                                              cW1, cb1, cW2, cb2, pos_out, N, E);
    node_kernel<<<(N + 63) / 64, NTHREADS, NODE_SMEM>>>(h, nW1, nb1, nW2, nb2, h_out, N);
}

// round 5
// speedup vs baseline: 3.0987x; 1.5582x over previous
#include <cuda_runtime.h>
#include <cuda_bf16.h>

#define TILE_E 128
#define NTHREADS 256
#define NMAX 50000

// Scratch (device globals: allocation-free rule)
__device__ float g_A[NMAX * 128];    // h @ eW1[0:128]   gathered by row
__device__ float g_B[NMAX * 128];    // h @ eW1[128:256] gathered by col
__device__ float g_agg[NMAX * 128];  // segment_sum(m2, row)
__device__ int   g_is64;             // edge_index dtype flag

__device__ __forceinline__ float silu(float x) { return x / (1.0f + __expf(-x)); }
__device__ __forceinline__ float4 silu4(float4 v) {
    return make_float4(silu(v.x), silu(v.y), silu(v.z), silu(v.w));
}
__device__ __forceinline__ void fma4(float4& a, float s, float4 w) {
    a.x = fmaf(s, w.x, a.x); a.y = fmaf(s, w.y, a.y);
    a.z = fmaf(s, w.z, a.z); a.w = fmaf(s, w.w, a.w);
}
__device__ __forceinline__ unsigned smem_u32(const void* p) {
    unsigned a;
    asm("{ .reg .u64 t; cvta.to.shared.u64 t, %1; cvt.u32.u64 %0, t; }" : "=r"(a) : "l"(p));
    return a;
}
// pack two fp32 into bf16-hi pair / bf16-lo pair
__device__ __forceinline__ void hilo2(float v0, float v1, unsigned& hp, unsigned& lp) {
    __nv_bfloat16 h0 = __float2bfloat16(v0), h1 = __float2bfloat16(v1);
    __nv_bfloat16 l0 = __float2bfloat16(v0 - __bfloat162float(h0));
    __nv_bfloat16 l1 = __float2bfloat16(v1 - __bfloat162float(h1));
    hp = (unsigned)__bfloat16_as_ushort(h0) | ((unsigned)__bfloat16_as_ushort(h1) << 16);
    lp = (unsigned)__bfloat16_as_ushort(l0) | ((unsigned)__bfloat16_as_ushort(l1) << 16);
}
__device__ __forceinline__ void ldsm4(unsigned r[4], unsigned addr) {
    asm volatile("ldmatrix.sync.aligned.m8n8.x4.shared.b16 {%0,%1,%2,%3}, [%4];"
                 : "=r"(r[0]), "=r"(r[1]), "=r"(r[2]), "=r"(r[3]) : "r"(addr));
}
__device__ __forceinline__ void mma_bf16(float d[4], const unsigned a[4], unsigned b0, unsigned b1) {
    asm volatile("mma.sync.aligned.m16n8k16.row.col.f32.bf16.bf16.f32 "
                 "{%0,%1,%2,%3}, {%4,%5,%6,%7}, {%8,%9}, {%0,%1,%2,%3};"
                 : "+f"(d[0]), "+f"(d[1]), "+f"(d[2]), "+f"(d[3])
                 : "r"(a[0]), "r"(a[1]), "r"(a[2]), "r"(a[3]), "r"(b0), "r"(b1));
}

// warp-level 16x128x128 GEMM, bf16 hi/lo 3-term fp32 emulation
// A tile: 16 rows x 128 cols bf16, row stride 272B. B: 128(out) x 128(k), stride 272B.
__device__ __forceinline__ void warp_gemm(unsigned aHi, unsigned aLo,
                                          unsigned bHi, unsigned bLo,
                                          unsigned aoff, unsigned boff, float (*d)[4]) {
    #pragma unroll
    for (int ks = 0; ks < 8; ks++) {
        unsigned ah[4], al[4];
        ldsm4(ah, aHi + aoff + ks * 32);
        ldsm4(al, aLo + aoff + ks * 32);
        #pragma unroll
        for (int np = 0; np < 8; np++) {
            unsigned bh[4], bl[4];
            unsigned ba = boff + np * 4352 + ks * 32;
            ldsm4(bh, bHi + ba);
            ldsm4(bl, bLo + ba);
            mma_bf16(d[np * 2],     ah, bh[0], bh[1]);
            mma_bf16(d[np * 2 + 1], ah, bh[2], bh[3]);
            mma_bf16(d[np * 2],     ah, bl[0], bl[1]);
            mma_bf16(d[np * 2 + 1], ah, bl[2], bl[3]);
            mma_bf16(d[np * 2],     al, bh[0], bh[1]);
            mma_bf16(d[np * 2 + 1], al, bh[2], bh[3]);
        }
    }
}

// SMEM byte layout for edge kernel
#define W2HI_B 4096
#define W2LO_B 38912
#define C1HI_B 73728
#define C1LO_B 108544
#define AT_B   143360     // 8 warps x (hi 4352 + lo 4352)
#define EDGE_SMEM 212992

// ---------------------------------------------------------------------------
__global__ void detect_kernel(const void* __restrict__ ei, int N, int E) {
    __shared__ int ok;
    if (threadIdx.x == 0) ok = 1;
    __syncthreads();
    int n = (E < 256) ? E : 256;
    if ((int)threadIdx.x < n) {
        long long v = ((const long long*)ei)[threadIdx.x];
        if (v < 0 || v >= (long long)N) atomicExch(&ok, 0);
    }
    __syncthreads();
    if (threadIdx.x == 0) g_is64 = ok;
}

__global__ void init_kernel(const float* __restrict__ pos, float* __restrict__ pos_out, int N) {
    int i = blockIdx.x * blockDim.x + threadIdx.x;
    if (i < N * 128) g_agg[i] = 0.0f;
    if (i < N * 3) pos_out[i] = pos[i];
}

// ---------------------------------------------------------------------------
// precompute: A = h @ eW1[0:128,:], B = h @ eW1[128:256,:]
// ---------------------------------------------------------------------------
#define PRE_SMEM ((64 * 132 + 16384) * 4)
__global__ __launch_bounds__(NTHREADS) void pre_kernel(
    const float* __restrict__ h, const float* __restrict__ eW1, int N)
{
    extern __shared__ float sm[];
    float* h_sm = sm;
    float* w_sm = sm + 64 * 132;
    int tid = threadIdx.x;
    int n0 = blockIdx.x * 64;
    for (int idx = tid; idx < 64 * 128; idx += NTHREADS) {
        int e = idx >> 7, k = idx & 127;
        int node = n0 + e;
        h_sm[e * 132 + k] = (node < N) ? h[node * 128 + k] : 0.0f;
    }
    const float4* hf4 = (const float4*)h_sm;
    int wid = tid >> 5, lane = tid & 31, ebase = wid * 8;

    for (int half = 0; half < 2; half++) {
        __syncthreads();
        for (int i = tid; i < 16384; i += NTHREADS) w_sm[i] = eW1[half * 16384 + i];
        __syncthreads();
        const float4* wf4 = (const float4*)w_sm;
        float4 acc[8];
        #pragma unroll
        for (int e = 0; e < 8; e++) acc[e] = make_float4(0.f, 0.f, 0.f, 0.f);
        for (int k0 = 0; k0 < 128; k0 += 4) {
            float4 w0 = wf4[(k0 + 0) * 32 + lane];
            float4 w1 = wf4[(k0 + 1) * 32 + lane];
            float4 w2 = wf4[(k0 + 2) * 32 + lane];
            float4 w3 = wf4[(k0 + 3) * 32 + lane];
            #pragma unroll
            for (int e = 0; e < 8; e++) {
                float4 mv = hf4[(ebase + e) * 33 + (k0 >> 2)];
                fma4(acc[e], mv.x, w0); fma4(acc[e], mv.y, w1);
                fma4(acc[e], mv.z, w2); fma4(acc[e], mv.w, w3);
            }
        }
        float* dst = (half == 0) ? g_A : g_B;
        #pragma unroll
        for (int e = 0; e < 8; e++) {
            int node = n0 + ebase + e;
            if (node < N) ((float4*)dst)[node * 32 + lane] = acc[e];
        }
    }
}

// ---------------------------------------------------------------------------
// fused edge kernel: warp-private mma.sync bf16 hi/lo pipeline, 128 edges/tile
// ---------------------------------------------------------------------------
__global__ __launch_bounds__(NTHREADS) void edge_kernel(
    const float* __restrict__ pos, const float* __restrict__ edge_attr,
    const void* __restrict__ ei_raw,
    const float* __restrict__ eW1, const float* __restrict__ eb1,
    const float* __restrict__ eW2, const float* __restrict__ eb2,
    const float* __restrict__ cW1, const float* __restrict__ cb1,
    const float* __restrict__ cW2, const float* __restrict__ cb2,
    float* __restrict__ pos_out, int N, int E)
{
    extern __shared__ float smf[];
    char* smc = (char*)smf;
    unsigned sbase = smem_u32(smf);
    int tid = threadIdx.x, wid = tid >> 5, lane = tid & 31;
    int g = lane >> 3, l = lane & 7;
    int qm = lane >> 2, qk = lane & 3;      // D-frag row / col-pair

    // sv: w_rn 0, w_ea 128, eb1 256, eb2 384, cb1 512, cw2 640, cb2 768
    float* sv = smf;
    for (int i = tid; i < 128; i += NTHREADS) {
        sv[i]       = eW1[256 * 128 + i];
        sv[128 + i] = eW1[257 * 128 + i];
        sv[256 + i] = eb1[i];
        sv[384 + i] = eb2[i];
        sv[512 + i] = cb1[i];
        sv[640 + i] = cW2[i];
    }
    if (tid == 0) sv[768] = cb2[0];

    // weights: B[o][k] = W[k][o], bf16 hi/lo, row stride 272B
    for (int idx = tid; idx < 16384; idx += NTHREADS) {
        int k = idx >> 7, o = idx & 127;
        unsigned off = (unsigned)(o * 272 + k * 2);
        float w = eW2[idx];
        __nv_bfloat16 hh = __float2bfloat16(w);
        *(__nv_bfloat16*)(smc + W2HI_B + off) = hh;
        *(__nv_bfloat16*)(smc + W2LO_B + off) = __float2bfloat16(w - __bfloat162float(hh));
        w = cW1[idx];
        hh = __float2bfloat16(w);
        *(__nv_bfloat16*)(smc + C1HI_B + off) = hh;
        *(__nv_bfloat16*)(smc + C1LO_B + off) = __float2bfloat16(w - __bfloat162float(hh));
    }
    __syncthreads();

    float cb2v = sv[768];
    int is64 = g_is64;
    const long long* ei64 = (const long long*)ei_raw;
    const int*       ei32 = (const int*)ei_raw;

    // per-lane phase1 constants (cols lane*4 .. +3)
    float4 wr = *(const float4*)&sv[lane * 4];
    float4 we = *(const float4*)&sv[128 + lane * 4];
    float4 bi = *(const float4*)&sv[256 + lane * 4];

    // per-warp A tile bases
    unsigned aHi = sbase + AT_B + wid * 8704;
    unsigned aLo = aHi + 4352;
    unsigned bW2h = sbase + W2HI_B, bW2l = sbase + W2LO_B;
    unsigned bC1h = sbase + C1HI_B, bC1l = sbase + C1LO_B;

    // ldmatrix lane offsets
    unsigned aoff = (unsigned)((l + ((g & 1) << 3)) * 272 + (g >> 1) * 16);
    unsigned boff = (unsigned)((l + ((g >> 1) << 3)) * 272 + (g & 1) * 16);

    int ntiles = (E + TILE_E - 1) / TILE_E;
    for (int t = blockIdx.x; t < ntiles; t += gridDim.x) {
        int e0w = t * TILE_E + wid * 16;     // this warp's first edge

        // --- meta (lanes 0..15 hold edge lane's data) ---
        int m_r = 0, m_c = 0;
        float m_rn = 1.0f, m_irn = 1.0f, m_ea = 0.0f, m_rx = 0.0f, m_ry = 0.0f, m_rz = 0.0f;
        if (lane < 16) {
            int e = e0w + lane;
            if (e < E) {
                int r, c;
                if (is64) { r = (int)ei64[e]; c = (int)ei64[E + e]; }
                else      { r = ei32[e];      c = ei32[E + e]; }
                r = min(max(r, 0), N - 1);
                c = min(max(c, 0), N - 1);
                float dx = pos[r * 3 + 0] - pos[c * 3 + 0];
                float dy = pos[r * 3 + 1] - pos[c * 3 + 1];
                float dz = pos[r * 3 + 2] - pos[c * 3 + 2];
                float nrm = sqrtf(dx * dx + dy * dy + dz * dz);
                float rn = fmaxf(nrm, 1e-8f);
                m_r = r; m_c = c; m_rn = rn; m_irn = 1.0f / rn;
                m_ea = edge_attr[e];
                m_rx = dx; m_ry = dy; m_rz = dz;
            }
        }

        // --- phase1: m = silu(A[row]+B[col]+rn*w_rn+ea*w_ea+eb1) -> hi/lo tile ---
        #pragma unroll
        for (int row = 0; row < 16; row++) {
            int rsrc = __shfl_sync(0xffffffffu, m_r, row);
            int csrc = __shfl_sync(0xffffffffu, m_c, row);
            float rn  = __shfl_sync(0xffffffffu, m_rn, row);
            float eav = __shfl_sync(0xffffffffu, m_ea, row);
            float4 a = *(const float4*)(g_A + rsrc * 128 + lane * 4);
            float4 b = *(const float4*)(g_B + csrc * 128 + lane * 4);
            float v0 = silu(fmaf(eav, we.x, fmaf(rn, wr.x, a.x + b.x)) + bi.x);
            float v1 = silu(fmaf(eav, we.y, fmaf(rn, wr.y, a.y + b.y)) + bi.y);
            float v2 = silu(fmaf(eav, we.z, fmaf(rn, wr.z, a.z + b.z)) + bi.z);
            float v3 = silu(fmaf(eav, we.w, fmaf(rn, wr.w, a.w + b.w)) + bi.w);
            unsigned hp0, hp1, lp0, lp1;
            hilo2(v0, v1, hp0, lp0); hilo2(v2, v3, hp1, lp1);
            unsigned off = (unsigned)(row * 272 + lane * 8);
            *(uint2*)(smc + (aHi - sbase) + off) = make_uint2(hp0, hp1);
            *(uint2*)(smc + (aLo - sbase) + off) = make_uint2(lp0, lp1);
        }
        __syncwarp();

        // --- GEMM2: D1 = m @ eW2 ---
        float d[16][4];
        #pragma unroll
        for (int i = 0; i < 16; i++) { d[i][0] = d[i][1] = d[i][2] = d[i][3] = 0.f; }
        warp_gemm(aHi, aLo, bW2h, bW2l, aoff, boff, d);

        // --- epilogue1: m2 = silu(D1 + eb2) -> tile (overwrite) + agg atomics ---
        int ri0 = __shfl_sync(0xffffffffu, m_r, qm);
        int ri8 = __shfl_sync(0xffffffffu, m_r, qm + 8);
        bool ok0 = (e0w + qm) < E, ok8 = (e0w + qm + 8) < E;
        float* ga0 = g_agg + ri0 * 128;
        float* ga8 = g_agg + ri8 * 128;
        #pragma unroll
        for (int nt = 0; nt < 16; nt++) {
            int o0 = nt * 8 + qk * 2;
            float e_0 = sv[384 + o0], e_1 = sv[384 + o0 + 1];
            float v0 = silu(d[nt][0] + e_0);
            float v1 = silu(d[nt][1] + e_1);
            float v2 = silu(d[nt][2] + e_0);
            float v3 = silu(d[nt][3] + e_1);
            unsigned hp, lp;
            hilo2(v0, v1, hp, lp);
            unsigned off = (unsigned)(qm * 272 + o0 * 2);
            *(unsigned*)(smc + (aHi - sbase) + off) = hp;
            *(unsigned*)(smc + (aLo - sbase) + off) = lp;
            hilo2(v2, v3, hp, lp);
            off = (unsigned)((qm + 8) * 272 + o0 * 2);
            *(unsigned*)(smc + (aHi - sbase) + off) = hp;
            *(unsigned*)(smc + (aLo - sbase) + off) = lp;
            if (ok0) { atomicAdd(ga0 + o0, v0); atomicAdd(ga0 + o0 + 1, v1); }
            if (ok8) { atomicAdd(ga8 + o0, v2); atomicAdd(ga8 + o0 + 1, v3); }
        }
        __syncwarp();

        // --- GEMM3: D2 = m2 @ cW1 ---
        #pragma unroll
        for (int i = 0; i < 16; i++) { d[i][0] = d[i][1] = d[i][2] = d[i][3] = 0.f; }
        warp_gemm(aHi, aLo, bC1h, bC1l, aoff, boff, d);

        // --- epilogue2: coord = silu(D2 + cb1) . cW2; pos atomics ---
        float pA = 0.0f, pB = 0.0f;
        #pragma unroll
        for (int nt = 0; nt < 16; nt++) {
            int o0 = nt * 8 + qk * 2;
            float c_0 = sv[512 + o0], c_1 = sv[512 + o0 + 1];
            float w_0 = sv[640 + o0], w_1 = sv[640 + o0 + 1];
            pA = fmaf(silu(d[nt][0] + c_0), w_0, pA);
            pA = fmaf(silu(d[nt][1] + c_1), w_1, pA);
            pB = fmaf(silu(d[nt][2] + c_0), w_0, pB);
            pB = fmaf(silu(d[nt][3] + c_1), w_1, pB);
        }
        pA += __shfl_xor_sync(0xffffffffu, pA, 1);
        pA += __shfl_xor_sync(0xffffffffu, pA, 2);
        pB += __shfl_xor_sync(0xffffffffu, pB, 1);
        pB += __shfl_xor_sync(0xffffffffu, pB, 2);
        float irn0 = __shfl_sync(0xffffffffu, m_irn, qm);
        float irn8 = __shfl_sync(0xffffffffu, m_irn, qm + 8);
        float rx0 = __shfl_sync(0xffffffffu, m_rx, qm), rx8 = __shfl_sync(0xffffffffu, m_rx, qm + 8);
        float ry0 = __shfl_sync(0xffffffffu, m_ry, qm), ry8 = __shfl_sync(0xffffffffu, m_ry, qm + 8);
        float rz0 = __shfl_sync(0xffffffffu, m_rz, qm), rz8 = __shfl_sync(0xffffffffu, m_rz, qm + 8);
        if (qk == 0) {
            if (ok0) {
                float s = (pA + cb2v) * irn0;
                atomicAdd(&pos_out[ri0 * 3 + 0], s * rx0);
                atomicAdd(&pos_out[ri0 * 3 + 1], s * ry0);
                atomicAdd(&pos_out[ri0 * 3 + 2], s * rz0);
            }
            if (ok8) {
                float s = (pB + cb2v) * irn8;
                atomicAdd(&pos_out[ri8 * 3 + 0], s * rx8);
                atomicAdd(&pos_out[ri8 * 3 + 1], s * ry8);
                atomicAdd(&pos_out[ri8 * 3 + 2], s * rz8);
            }
        }
        __syncwarp();
    }
}

// ---------------------------------------------------------------------------
// node MLP: hn = silu([h,agg] @ nW1 + nb1); h_new = h + hn @ nW2 + nb2
// ---------------------------------------------------------------------------
#define NODE_SMEM ((64 * 260 + 16384 + 64 * 132) * 4)
__global__ __launch_bounds__(NTHREADS) void node_kernel(
    const float* __restrict__ h,
    const float* __restrict__ nW1, const float* __restrict__ nb1,
    const float* __restrict__ nW2, const float* __restrict__ nb2,
    float* __restrict__ h_out, int N)
{
    extern __shared__ float sm[];
    float* x_sm  = sm;
    float* w_sm  = sm + 16640;
    float* hn_sm = sm + 33024;

    int tid = threadIdx.x, wid = tid >> 5, lane = tid & 31, ebase = wid * 8;
    int n0 = blockIdx.x * 64;
    for (int idx = tid; idx < 64 * 256; idx += NTHREADS) {
        int e = idx >> 8, k = idx & 255;
        int node = n0 + e;
        float v = 0.0f;
        if (node < N) v = (k < 128) ? h[node * 128 + k] : g_agg[node * 128 + (k - 128)];
        x_sm[e * 260 + k] = v;
    }
    const float4* Xf = (const float4*)x_sm;

    float4 acc[8];
    float4 bn1 = ((const float4*)nb1)[lane];
    #pragma unroll
    for (int e = 0; e < 8; e++) acc[e] = bn1;

    for (int half = 0; half < 2; half++) {
        __syncthreads();
        for (int i = tid; i < 16384; i += NTHREADS) w_sm[i] = nW1[half * 16384 + i];
        __syncthreads();
        const float4* Wf = (const float4*)w_sm;
        for (int k0 = 0; k0 < 128; k0 += 4) {
            float4 w0 = Wf[(k0 + 0) * 32 + lane];
            float4 w1 = Wf[(k0 + 1) * 32 + lane];
            float4 w2 = Wf[(k0 + 2) * 32 + lane];
            float4 w3 = Wf[(k0 + 3) * 32 + lane];
            #pragma unroll
            for (int e = 0; e < 8; e++) {
                float4 mv = Xf[(ebase + e) * 65 + half * 32 + (k0 >> 2)];
                fma4(acc[e], mv.x, w0); fma4(acc[e], mv.y, w1);
                fma4(acc[e], mv.z, w2); fma4(acc[e], mv.w, w3);
            }
        }
    }
    #pragma unroll
    for (int e = 0; e < 8; e++)
        ((float4*)hn_sm)[(ebase + e) * 33 + lane] = silu4(acc[e]);
    __syncthreads();
    for (int i = tid; i < 16384; i += NTHREADS) w_sm[i] = nW2[i];
    __syncthreads();

    const float4* Wf = (const float4*)w_sm;
    const float4* Hf = (const float4*)hn_sm;
    float4 bn2 = ((const float4*)nb2)[lane];
    #pragma unroll
    for (int e = 0; e < 8; e++) acc[e] = bn2;
    for (int k0 = 0; k0 < 128; k0 += 4) {
        float4 w0 = Wf[(k0 + 0) * 32 + lane];
        float4 w1 = Wf[(k0 + 1) * 32 + lane];
        float4 w2 = Wf[(k0 + 2) * 32 + lane];
        float4 w3 = Wf[(k0 + 3) * 32 + lane];
        #pragma unroll
        for (int e = 0; e < 8; e++) {
            float4 mv = Hf[(ebase + e) * 33 + (k0 >> 2)];
            fma4(acc[e], mv.x, w0); fma4(acc[e], mv.y, w1);
            fma4(acc[e], mv.z, w2); fma4(acc[e], mv.w, w3);
        }
    }
    #pragma unroll
    for (int e = 0; e < 8; e++) {
        int node = n0 + ebase + e;
        if (node < N) {
            float4 r = Xf[(ebase + e) * 65 + lane];
            acc[e].x += r.x; acc[e].y += r.y; acc[e].z += r.z; acc[e].w += r.w;
            ((float4*)h_out)[node * 32 + lane] = acc[e];
        }
    }
}

// ---------------------------------------------------------------------------
extern "C" void kernel_launch(void* const* d_in, const int* in_sizes, int n_in,
                              void* d_out, int out_size)
{
    const float* h   = (const float*)d_in[0];
    const float* pos = (const float*)d_in[1];
    const float* ea  = (const float*)d_in[2];
    const void*  ei  = d_in[3];
    const float* eW1 = (const float*)d_in[4];
    const float* eb1 = (const float*)d_in[5];
    const float* eW2 = (const float*)d_in[6];
    const float* eb2 = (const float*)d_in[7];
    const float* nW1 = (const float*)d_in[8];
    const float* nb1 = (const float*)d_in[9];
    const float* nW2 = (const float*)d_in[10];
    const float* nb2 = (const float*)d_in[11];
    const float* cW1 = (const float*)d_in[12];
    const float* cb1 = (const float*)d_in[13];
    const float* cW2 = (const float*)d_in[14];
    const float* cb2 = (const float*)d_in[15];

    int N = in_sizes[0] / 128;
    int E = in_sizes[2];
    float* h_out   = (float*)d_out;
    float* pos_out = h_out + (size_t)N * 128;

    cudaFuncSetAttribute(pre_kernel,  cudaFuncAttributeMaxDynamicSharedMemorySize, PRE_SMEM);
    cudaFuncSetAttribute(edge_kernel, cudaFuncAttributeMaxDynamicSharedMemorySize, EDGE_SMEM);
    cudaFuncSetAttribute(node_kernel, cudaFuncAttributeMaxDynamicSharedMemorySize, NODE_SMEM);

    int nsm = 148;
    cudaDeviceGetAttribute(&nsm, cudaDevAttrMultiProcessorCount, 0);

    detect_kernel<<<1, 256>>>(ei, N, E);
    init_kernel<<<(N * 128 + 255) / 256, 256>>>(pos, pos_out, N);
    pre_kernel<<<(N + 63) / 64, NTHREADS, PRE_SMEM>>>(h, eW1, N);
    edge_kernel<<<nsm, NTHREADS, EDGE_SMEM>>>(pos, ea, ei, eW1, eb1, eW2, eb2,
                                              cW1, cb1, cW2, cb2, pos_out, N, E);
    node_kernel<<<(N + 63) / 64, NTHREADS, NODE_SMEM>>>(h, nW1, nb1, nW2, nb2, h_out, N);
}